// round 1
// baseline (speedup 1.0000x reference)
#include <cuda_runtime.h>

#define NN 50000
#define HH 256
#define EE 800000

// ---------------- scratch (static device globals; no allocation) ----------------
__device__ float g_fts[NN * HH];           // 51.2 MB
__device__ float g_embed[2][NN * HH];      // 102.4 MB (per-side, reused)
__device__ int   g_cnt[4][NN];             // histogram -> cursor
__device__ int   g_rowptr[4][NN + 1];
__device__ int   g_srcs[4][EE];
__device__ float g_vals[4][EE];
__device__ float g_sp[4][HH];              // colsum of tanh(fc(embed))
__device__ float g_beta[4];

// ---------------- f32x2 packed helpers ----------------
__device__ __forceinline__ unsigned long long pk2(float lo, float hi) {
    unsigned long long r;
    asm("mov.b64 %0,{%1,%2};" : "=l"(r) : "f"(lo), "f"(hi));
    return r;
}
__device__ __forceinline__ void upk2(unsigned long long v, float &lo, float &hi) {
    asm("mov.b64 {%0,%1},%2;" : "=f"(lo), "=f"(hi) : "l"(v));
}
__device__ __forceinline__ unsigned long long ffma2(unsigned long long a,
                                                    unsigned long long b,
                                                    unsigned long long c) {
    unsigned long long d;
    asm("fma.rn.f32x2 %0,%1,%2,%3;" : "=l"(d) : "l"(a), "l"(b), "l"(c));
    return d;
}

// ---------------- init: zero counters + colsum accumulators ----------------
__global__ void k_init() {
    int i = blockIdx.x * blockDim.x + threadIdx.x;
    int tot = 4 * NN;
    for (int x = i; x < tot; x += gridDim.x * blockDim.x) ((int*)g_cnt)[x] = 0;
    if (i < 4 * HH) ((float*)g_sp)[i] = 0.f;
}

// ---------------- CSR build ----------------
__global__ void k_hist(const int* __restrict__ idx, int m) {
    int i = blockIdx.x * blockDim.x + threadIdx.x;
    if (i < EE) atomicAdd(&g_cnt[m][idx[i]], 1);   // idx[0:E] = dst
}

__global__ void k_scan() {     // grid = 4 (one block per metapath), 1024 threads
    int m = blockIdx.x;
    int t = threadIdx.x;
    const int PER = (NN + 1023) / 1024;   // 49
    int b = t * PER;
    int e = b + PER; if (e > NN) e = NN;
    int s = 0;
    for (int i = b; i < e; i++) s += g_cnt[m][i];
    __shared__ int part[1024];
    part[t] = s;
    __syncthreads();
    for (int off = 1; off < 1024; off <<= 1) {   // inclusive Hillis-Steele
        int v = (t >= off) ? part[t - off] : 0;
        __syncthreads();
        part[t] += v;
        __syncthreads();
    }
    int run = part[t] - s;                       // exclusive prefix of chunks
    for (int i = b; i < e; i++) {
        int c = g_cnt[m][i];
        g_rowptr[m][i] = run;
        g_cnt[m][i] = run;                       // becomes scatter cursor
        run += c;
    }
    if (t == 0) g_rowptr[m][NN] = EE;
}

__global__ void k_scatter(const int* __restrict__ idx, const float* __restrict__ val, int m) {
    int i = blockIdx.x * blockDim.x + threadIdx.x;
    if (i < EE) {
        int d = idx[i];           // dst
        int s = idx[EE + i];      // src
        int pos = atomicAdd(&g_cnt[m][d], 1);
        g_srcs[m][pos] = s;
        g_vals[m][pos] = val[i];
    }
}

// ---------------- SGEMM (FFMA2), C = A @ W^T ----------------
// MODE 0: C -> g_fts.   MODE 1: colsum of tanh(C + bias) -> g_sp[spIdx] (atomic).
#define BM 128
#define BN 64
#define BK 32

template <int MODE>
__global__ __launch_bounds__(256) void k_gemm(const float* __restrict__ Aext,
                                              int abuf,      // <0: use Aext, else g_embed[abuf]
                                              const float* __restrict__ W,
                                              const float* __restrict__ bias,
                                              int spIdx) {
    __shared__ float As[BK][BM];
    __shared__ float Ws[BK][BN];
    __shared__ float red[BN];

    const float* A = (abuf < 0) ? Aext : g_embed[abuf];

    int tid = threadIdx.x;
    int tx = tid & 15, ty = tid >> 4;
    int rowBase = blockIdx.x * BM;
    int colBase = blockIdx.y * BN;

    unsigned long long c[4][4];
#pragma unroll
    for (int i = 0; i < 4; i++)
#pragma unroll
        for (int j = 0; j < 4; j++) c[i][j] = 0ULL;

    for (int kt = 0; kt < HH; kt += BK) {
#pragma unroll
        for (int l = 0; l < 4; l++) {               // A tile: 128x32 = 1024 float4
            int idx = tid + l * 256;
            int r = idx >> 3;
            int k4 = (idx & 7) << 2;
            int gr = rowBase + r;
            float4 v = make_float4(0.f, 0.f, 0.f, 0.f);
            if (gr < NN) v = *(const float4*)&A[gr * HH + kt + k4];
            As[k4 + 0][r] = v.x; As[k4 + 1][r] = v.y;
            As[k4 + 2][r] = v.z; As[k4 + 3][r] = v.w;
        }
#pragma unroll
        for (int l = 0; l < 2; l++) {               // W tile: 64x32 = 512 float4
            int idx = tid + l * 256;
            int r = idx >> 3;
            int k4 = (idx & 7) << 2;
            float4 v = *(const float4*)&W[(colBase + r) * HH + kt + k4];
            Ws[k4 + 0][r] = v.x; Ws[k4 + 1][r] = v.y;
            Ws[k4 + 2][r] = v.z; Ws[k4 + 3][r] = v.w;
        }
        __syncthreads();
#pragma unroll
        for (int k = 0; k < BK; k++) {
            ulonglong2 A0 = *(const ulonglong2*)&As[k][ty * 8];
            ulonglong2 A1 = *(const ulonglong2*)&As[k][ty * 8 + 4];
            float4 bv = *(const float4*)&Ws[k][tx * 4];
            unsigned long long bp[4] = {pk2(bv.x, bv.x), pk2(bv.y, bv.y),
                                        pk2(bv.z, bv.z), pk2(bv.w, bv.w)};
            unsigned long long ap[4] = {A0.x, A0.y, A1.x, A1.y};
#pragma unroll
            for (int ip = 0; ip < 4; ip++)
#pragma unroll
                for (int j = 0; j < 4; j++)
                    c[ip][j] = ffma2(ap[ip], bp[j], c[ip][j]);
        }
        __syncthreads();
    }

    if (MODE == 0) {
#pragma unroll
        for (int ip = 0; ip < 4; ip++) {
            float lo[4], hi[4];
#pragma unroll
            for (int j = 0; j < 4; j++) upk2(c[ip][j], lo[j], hi[j]);
            int r0 = rowBase + ty * 8 + ip * 2;
            if (r0 < NN)
                *(float4*)&g_fts[r0 * HH + colBase + tx * 4] =
                    make_float4(lo[0], lo[1], lo[2], lo[3]);
            if (r0 + 1 < NN)
                *(float4*)&g_fts[(r0 + 1) * HH + colBase + tx * 4] =
                    make_float4(hi[0], hi[1], hi[2], hi[3]);
        }
    } else {
        float4 bb = *(const float4*)&bias[colBase + tx * 4];
        float bcol[4] = {bb.x, bb.y, bb.z, bb.w};
        float part[4] = {0.f, 0.f, 0.f, 0.f};
#pragma unroll
        for (int ip = 0; ip < 4; ip++) {
            float lo[4], hi[4];
#pragma unroll
            for (int j = 0; j < 4; j++) upk2(c[ip][j], lo[j], hi[j]);
            int r0 = rowBase + ty * 8 + ip * 2;
            if (r0 < NN) {
#pragma unroll
                for (int j = 0; j < 4; j++) part[j] += tanhf(lo[j] + bcol[j]);
            }
            if (r0 + 1 < NN) {
#pragma unroll
                for (int j = 0; j < 4; j++) part[j] += tanhf(hi[j] + bcol[j]);
            }
        }
        if (tid < BN) red[tid] = 0.f;
        __syncthreads();
#pragma unroll
        for (int j = 0; j < 4; j++) atomicAdd(&red[tx * 4 + j], part[j]);
        __syncthreads();
        if (tid < BN) atomicAdd(&g_sp[spIdx][colBase + tid], red[tid]);
    }
}

// ---------------- CSR SpMM + bias + PReLU ----------------
__global__ __launch_bounds__(256) void k_spmm(int m, int obuf,
                                              const float* __restrict__ bias,
                                              const float* __restrict__ slope) {
    int r = blockIdx.x * 4 + (threadIdx.x >> 6);
    int f = (threadIdx.x & 63) << 2;
    if (r >= NN) return;
    const int* __restrict__ rowptr = g_rowptr[m];
    const int* __restrict__ srcs = g_srcs[m];
    const float* __restrict__ vals = g_vals[m];
    int s = rowptr[r], e = rowptr[r + 1];
    float4 acc = make_float4(0.f, 0.f, 0.f, 0.f);
    int i = s;
    for (; i + 1 < e; i += 2) {
        int s0 = srcs[i], s1 = srcs[i + 1];
        float v0 = vals[i], v1 = vals[i + 1];
        float4 x0 = *(const float4*)&g_fts[s0 * HH + f];
        float4 x1 = *(const float4*)&g_fts[s1 * HH + f];
        acc.x += v0 * x0.x + v1 * x1.x;
        acc.y += v0 * x0.y + v1 * x1.y;
        acc.z += v0 * x0.z + v1 * x1.z;
        acc.w += v0 * x0.w + v1 * x1.w;
    }
    if (i < e) {
        int s0 = srcs[i]; float v0 = vals[i];
        float4 x0 = *(const float4*)&g_fts[s0 * HH + f];
        acc.x += v0 * x0.x; acc.y += v0 * x0.y;
        acc.z += v0 * x0.z; acc.w += v0 * x0.w;
    }
    float a = slope[0];
    float4 bb = *(const float4*)&bias[f];
    float4 o;
    o.x = acc.x + bb.x; o.x = o.x > 0.f ? o.x : a * o.x;
    o.y = acc.y + bb.y; o.y = o.y > 0.f ? o.y : a * o.y;
    o.z = acc.z + bb.z; o.z = o.z > 0.f ? o.z : a * o.z;
    o.w = acc.w + bb.w; o.w = o.w > 0.f ? o.w : a * o.w;
    *(float4*)&g_embed[obuf][r * HH + f] = o;
}

// ---------------- attention softmax over metapaths (one side) ----------------
__global__ void k_beta(const float* __restrict__ att, int side) {
    __shared__ float red[256];
    __shared__ float sres[2];
    int t = threadIdx.x;
    float a = att[t];
    for (int p = 0; p < 2; p++) {
        red[t] = g_sp[side * 2 + p][t] * a;
        __syncthreads();
        for (int off = 128; off > 0; off >>= 1) {
            if (t < off) red[t] += red[t + off];
            __syncthreads();
        }
        if (t == 0) sres[p] = red[0];
        __syncthreads();
    }
    if (t == 0) {
        float s0 = sres[0] / (float)NN, s1 = sres[1] / (float)NN;
        float mx = fmaxf(s0, s1);
        float e0 = expf(s0 - mx), e1 = expf(s1 - mx);
        float inv = 1.f / (e0 + e1);
        g_beta[side * 2 + 0] = e0 * inv;
        g_beta[side * 2 + 1] = e1 * inv;
    }
}

// ---------------- z = beta0*e0 + beta1*e1 ----------------
__global__ void k_combine(int side, float* __restrict__ out) {
    float b0 = g_beta[side * 2], b1 = g_beta[side * 2 + 1];
    const float4* e0 = (const float4*)g_embed[0];
    const float4* e1 = (const float4*)g_embed[1];
    float4* o = (float4*)(out + (size_t)side * NN * HH);
    int tot = NN * HH / 4;
    for (int i = blockIdx.x * blockDim.x + threadIdx.x; i < tot;
         i += gridDim.x * blockDim.x) {
        float4 x = e0[i], y = e1[i];
        o[i] = make_float4(b0 * x.x + b1 * y.x, b0 * x.y + b1 * y.y,
                           b0 * x.z + b1 * y.z, b0 * x.w + b1 * y.w);
    }
}

// ---------------- launch ----------------
extern "C" void kernel_launch(void* const* d_in, const int* in_sizes, int n_in,
                              void* d_out, int out_size) {
    const float* h_side[2] = {(const float*)d_in[0], (const float*)d_in[1]};
    const int*   idx[4] = {(const int*)d_in[2], (const int*)d_in[4],
                           (const int*)d_in[6], (const int*)d_in[8]};
    const float* val[4] = {(const float*)d_in[3], (const float*)d_in[5],
                           (const float*)d_in[7], (const float*)d_in[9]};
    const float* Wm[4] = {(const float*)d_in[10], (const float*)d_in[13],
                          (const float*)d_in[16], (const float*)d_in[19]};
    const float* bm[4] = {(const float*)d_in[11], (const float*)d_in[14],
                          (const float*)d_in[17], (const float*)d_in[20]};
    const float* am[4] = {(const float*)d_in[12], (const float*)d_in[15],
                          (const float*)d_in[18], (const float*)d_in[21]};
    const float* fcW[2] = {(const float*)d_in[22], (const float*)d_in[25]};
    const float* fcb[2] = {(const float*)d_in[23], (const float*)d_in[26]};
    const float* att[2] = {(const float*)d_in[24], (const float*)d_in[27]};
    float* out = (float*)d_out;

    k_init<<<784, 256>>>();
    for (int m = 0; m < 4; m++)
        k_hist<<<(EE + 255) / 256, 256>>>(idx[m], m);
    k_scan<<<4, 1024>>>();
    for (int m = 0; m < 4; m++)
        k_scatter<<<(EE + 255) / 256, 256>>>(idx[m], val[m], m);

    dim3 ggrid((NN + BM - 1) / BM, HH / BN);   // 391 x 4
    for (int side = 0; side < 2; side++) {
        for (int p = 0; p < 2; p++) {
            int m = side * 2 + p;
            k_gemm<0><<<ggrid, 256>>>(h_side[side], -1, Wm[m], nullptr, 0);
            k_spmm<<<(NN + 3) / 4, 256>>>(m, p, bm[m], am[m]);
            k_gemm<1><<<ggrid, 256>>>(nullptr, p, fcW[side], fcb[side], m);
        }
        k_beta<<<1, 256>>>(att[side], side);
        k_combine<<<2048, 256>>>(side, out);
    }
}

// round 3
// speedup vs baseline: 1.7968x; 1.7968x over previous
#include <cuda_runtime.h>
#include <cuda_bf16.h>
#include <cstdint>

#define NN 50000
#define HH 256
#define EE 800000

// ---------------- scratch (static device globals; no allocation) ----------------
__device__ float g_fts[NN * HH];               // GEMM output (fp32)
__device__ float g_embed[2][NN * HH];          // per-side metapath embeddings (fp32)
__device__ int   g_cnt[4][NN];
__device__ int   g_rowptr[4][NN + 1];
__device__ int   g_srcs[4][EE];
__device__ float g_vals[4][EE];
__device__ float g_sp[4][HH];
__device__ float g_beta[4];

// bf16 hi/lo split operands for tensor GEMMs
__device__ __nv_bfloat16 g_ah[NN * HH], g_al[NN * HH];          // activation (h side)
__device__ __nv_bfloat16 g_ebh[2][NN * HH], g_ebl[2][NN * HH];  // embeds (fc input)
__device__ __nv_bfloat16 g_wh[6][HH * HH], g_wl[6][HH * HH];    // weights

// ---------------- helpers ----------------
__device__ __forceinline__ uint32_t smem_u32(const void* p) {
    uint32_t a;
    asm("{ .reg .u64 t; cvta.to.shared.u64 t, %1; cvt.u32.u64 %0, t; }" : "=r"(a) : "l"(p));
    return a;
}
__device__ __forceinline__ void ldsm4(uint32_t* r, uint32_t addr) {
    asm volatile("ldmatrix.sync.aligned.m8n8.x4.shared.b16 {%0,%1,%2,%3}, [%4];"
                 : "=r"(r[0]), "=r"(r[1]), "=r"(r[2]), "=r"(r[3]) : "r"(addr));
}
__device__ __forceinline__ void mma16816(float* c, const uint32_t* a,
                                         uint32_t b0, uint32_t b1) {
    asm volatile(
        "mma.sync.aligned.m16n8k16.row.col.f32.bf16.bf16.f32 "
        "{%0,%1,%2,%3}, {%4,%5,%6,%7}, {%8,%9}, {%0,%1,%2,%3};"
        : "+f"(c[0]), "+f"(c[1]), "+f"(c[2]), "+f"(c[3])
        : "r"(a[0]), "r"(a[1]), "r"(a[2]), "r"(a[3]), "r"(b0), "r"(b1));
}
__device__ __forceinline__ float tanhA(float x) {
    float y;
    asm("tanh.approx.f32 %0, %1;" : "=f"(y) : "f"(x));
    return y;
}

// ---------------- init ----------------
__global__ void k_init() {
    int i = blockIdx.x * blockDim.x + threadIdx.x;
    int tot = 4 * NN;
    for (int x = i; x < tot; x += gridDim.x * blockDim.x) ((int*)g_cnt)[x] = 0;
    if (i < 4 * HH) ((float*)g_sp)[i] = 0.f;
}

// ---------------- CSR build ----------------
__global__ void k_hist(const int* __restrict__ idx, int m) {
    int i = blockIdx.x * blockDim.x + threadIdx.x;
    if (i < EE) atomicAdd(&g_cnt[m][idx[i]], 1);
}

__global__ void k_scan() {
    int m = blockIdx.x;
    int t = threadIdx.x;
    const int PER = (NN + 1023) / 1024;
    int b = t * PER;
    int e = b + PER; if (e > NN) e = NN;
    int s = 0;
    for (int i = b; i < e; i++) s += g_cnt[m][i];
    __shared__ int part[1024];
    part[t] = s;
    __syncthreads();
    for (int off = 1; off < 1024; off <<= 1) {
        int v = (t >= off) ? part[t - off] : 0;
        __syncthreads();
        part[t] += v;
        __syncthreads();
    }
    int run = part[t] - s;
    for (int i = b; i < e; i++) {
        int c = g_cnt[m][i];
        g_rowptr[m][i] = run;
        g_cnt[m][i] = run;
        run += c;
    }
    if (t == 0) g_rowptr[m][NN] = EE;
}

__global__ void k_scatter(const int* __restrict__ idx, const float* __restrict__ val, int m) {
    int i = blockIdx.x * blockDim.x + threadIdx.x;
    if (i < EE) {
        int d = idx[i];
        int s = idx[EE + i];
        int pos = atomicAdd(&g_cnt[m][d], 1);
        g_srcs[m][pos] = s;
        g_vals[m][pos] = val[i];
    }
}

// ---------------- bf16 hi/lo conversions ----------------
__device__ __forceinline__ void split4(float4 v, __nv_bfloat16* hi, __nv_bfloat16* lo) {
    __nv_bfloat16 h0 = __float2bfloat16(v.x), h1 = __float2bfloat16(v.y);
    __nv_bfloat16 h2 = __float2bfloat16(v.z), h3 = __float2bfloat16(v.w);
    hi[0] = h0; hi[1] = h1; hi[2] = h2; hi[3] = h3;
    lo[0] = __float2bfloat16(v.x - __bfloat162float(h0));
    lo[1] = __float2bfloat16(v.y - __bfloat162float(h1));
    lo[2] = __float2bfloat16(v.z - __bfloat162float(h2));
    lo[3] = __float2bfloat16(v.w - __bfloat162float(h3));
}

__global__ void k_conva(const float* __restrict__ X) {
    int tot = NN * HH / 4;
    for (int i = blockIdx.x * blockDim.x + threadIdx.x; i < tot;
         i += gridDim.x * blockDim.x) {
        float4 v = ((const float4*)X)[i];
        __nv_bfloat16 hi[4], lo[4];
        split4(v, hi, lo);
        *(uint2*)&g_ah[i * 4] = *(uint2*)hi;
        *(uint2*)&g_al[i * 4] = *(uint2*)lo;
    }
}

__global__ void k_convw(const float* __restrict__ X, int widx) {
    int tot = HH * HH / 4;
    for (int i = blockIdx.x * blockDim.x + threadIdx.x; i < tot;
         i += gridDim.x * blockDim.x) {
        float4 v = ((const float4*)X)[i];
        __nv_bfloat16 hi[4], lo[4];
        split4(v, hi, lo);
        *(uint2*)&g_wh[widx][i * 4] = *(uint2*)hi;
        *(uint2*)&g_wl[widx][i * 4] = *(uint2*)lo;
    }
}

// ---------------- HMMA GEMM: C = A @ W^T  (bf16 hi/lo split, fp32 accum) ----------------
// CTA tile 128x128, 8 warps (warp tile 32x64), K chunks of 64.
// MODE 0: C -> g_fts.   MODE 1: colsum of tanh(C + bias) -> g_sp[spIdx].
#define ASTRIDE 72                       // smem row stride in bf16 elems
#define TILE_E (128 * ASTRIDE)           // elems per smem tile
#define SMEM_SZ (4 * TILE_E * 2 + 512)   // 4 tiles + red[128]

template <int MODE>
__global__ __launch_bounds__(256) void k_mma(int asel, int widx,
                                             const float* __restrict__ bias,
                                             int spIdx) {
    extern __shared__ char smraw[];
    __nv_bfloat16* sAh = (__nv_bfloat16*)smraw;
    __nv_bfloat16* sAl = sAh + TILE_E;
    __nv_bfloat16* sBh = sAl + TILE_E;
    __nv_bfloat16* sBl = sBh + TILE_E;
    float* red = (float*)(sBl + TILE_E);

    const __nv_bfloat16 *Ah, *Al;
    if (asel == 0) { Ah = g_ah; Al = g_al; }
    else           { Ah = g_ebh[asel - 1]; Al = g_ebl[asel - 1]; }
    const __nv_bfloat16* Bh = g_wh[widx];
    const __nv_bfloat16* Bl = g_wl[widx];

    int tid = threadIdx.x, lane = tid & 31, wid = tid >> 5;
    int warp_m = wid & 3, warp_n = wid >> 2;
    int rowBase = blockIdx.x * 128;
    int colBase = blockIdx.y * 128;

    uint32_t sb = smem_u32(smraw);
    uint32_t uAh = sb, uAl = sb + TILE_E * 2, uBh = sb + 2 * TILE_E * 2,
             uBl = sb + 3 * TILE_E * 2;

    float acc[2][8][4];
#pragma unroll
    for (int i = 0; i < 2; i++)
#pragma unroll
        for (int j = 0; j < 8; j++)
#pragma unroll
            for (int q = 0; q < 4; q++) acc[i][j][q] = 0.f;

    for (int kb = 0; kb < 4; kb++) {
        if (kb) __syncthreads();
        // ---- gmem -> smem: 4 tiles of 128x64 bf16 ----
#pragma unroll
        for (int l = 0; l < 4; l++) {
            int idx = tid + l * 256;
            int r = idx >> 3, c = (idx & 7) * 8;
            int so = r * ASTRIDE + c;
            int gr = rowBase + r;
            uint4 vh = make_uint4(0, 0, 0, 0), vl = make_uint4(0, 0, 0, 0);
            if (gr < NN) {
                vh = *(const uint4*)&Ah[gr * HH + kb * 64 + c];
                vl = *(const uint4*)&Al[gr * HH + kb * 64 + c];
            }
            *(uint4*)&sAh[so] = vh;
            *(uint4*)&sAl[so] = vl;
            int gb = (colBase + r) * HH + kb * 64 + c;
            *(uint4*)&sBh[so] = *(const uint4*)&Bh[gb];
            *(uint4*)&sBl[so] = *(const uint4*)&Bl[gb];
        }
        __syncthreads();

#pragma unroll
        for (int ks = 0; ks < 4; ks++) {
            // fragment loads
            uint32_t ah[2][4], al[2][4], bh[4][4], bl[4][4];
            uint32_t lrow = (uint32_t)(lane & 15);
            uint32_t lcol = (uint32_t)((lane >> 4) * 8 + ks * 16);
#pragma unroll
            for (int mt = 0; mt < 2; mt++) {
                uint32_t off = ((warp_m * 32 + mt * 16 + lrow) * ASTRIDE + lcol) * 2;
                ldsm4(ah[mt], uAh + off);
                ldsm4(al[mt], uAl + off);
            }
#pragma unroll
            for (int nt = 0; nt < 4; nt++) {
                uint32_t off = ((warp_n * 64 + nt * 16 + lrow) * ASTRIDE + lcol) * 2;
                ldsm4(bh[nt], uBh + off);
                ldsm4(bl[nt], uBl + off);
            }
            // mma: 3 passes share accumulators
#pragma unroll
            for (int mt = 0; mt < 2; mt++)
#pragma unroll
                for (int nt = 0; nt < 4; nt++)
#pragma unroll
                    for (int h = 0; h < 2; h++) {
                        float* c = acc[mt][nt * 2 + h];
                        mma16816(c, ah[mt], bh[nt][h], bh[nt][h + 2]);  // hi*hi
                        mma16816(c, ah[mt], bl[nt][h], bl[nt][h + 2]);  // hi*lo
                        mma16816(c, al[mt], bh[nt][h], bh[nt][h + 2]);  // lo*hi
                    }
        }
    }

    // ---------------- epilogue ----------------
    if (MODE == 0) {
#pragma unroll
        for (int mt = 0; mt < 2; mt++) {
            int row0 = rowBase + warp_m * 32 + mt * 16 + (lane >> 2);
#pragma unroll
            for (int n = 0; n < 8; n++) {
                int col = colBase + warp_n * 64 + (n >> 1) * 16 + (n & 1) * 8 +
                          (lane & 3) * 2;
                float* c = acc[mt][n];
                if (row0 < NN)
                    *(float2*)&g_fts[row0 * HH + col] = make_float2(c[0], c[1]);
                if (row0 + 8 < NN)
                    *(float2*)&g_fts[(row0 + 8) * HH + col] = make_float2(c[2], c[3]);
            }
        }
    } else {
        for (int i = tid; i < 128; i += 256) red[i] = 0.f;
        __syncthreads();
#pragma unroll
        for (int n = 0; n < 8; n++) {
            int lcol = warp_n * 64 + (n >> 1) * 16 + (n & 1) * 8 + (lane & 3) * 2;
            float b0 = bias[colBase + lcol], b1 = bias[colBase + lcol + 1];
            float s0 = 0.f, s1 = 0.f;
#pragma unroll
            for (int mt = 0; mt < 2; mt++) {
                int row0 = rowBase + warp_m * 32 + mt * 16 + (lane >> 2);
                float* c = acc[mt][n];
                if (row0 < NN)     { s0 += tanhA(c[0] + b0); s1 += tanhA(c[1] + b1); }
                if (row0 + 8 < NN) { s0 += tanhA(c[2] + b0); s1 += tanhA(c[3] + b1); }
            }
            s0 += __shfl_xor_sync(0xffffffffu, s0, 4);
            s0 += __shfl_xor_sync(0xffffffffu, s0, 8);
            s0 += __shfl_xor_sync(0xffffffffu, s0, 16);
            s1 += __shfl_xor_sync(0xffffffffu, s1, 4);
            s1 += __shfl_xor_sync(0xffffffffu, s1, 8);
            s1 += __shfl_xor_sync(0xffffffffu, s1, 16);
            if (lane < 4) {
                int c0 = warp_n * 64 + (n >> 1) * 16 + (n & 1) * 8 + lane * 2;
                atomicAdd(&red[c0], s0);
                atomicAdd(&red[c0 + 1], s1);
            }
        }
        __syncthreads();
        if (tid < 128) atomicAdd(&g_sp[spIdx][colBase + tid], red[tid]);
    }
}

// ---------------- CSR SpMM + bias + PReLU (+ bf16 hi/lo conversion) ----------------
__global__ __launch_bounds__(256) void k_spmm(int m, int obuf,
                                              const float* __restrict__ bias,
                                              const float* __restrict__ slope) {
    int r = blockIdx.x * 4 + (threadIdx.x >> 6);
    int f = (threadIdx.x & 63) << 2;
    if (r >= NN) return;
    const int* __restrict__ rowptr = g_rowptr[m];
    const int* __restrict__ srcs = g_srcs[m];
    const float* __restrict__ vals = g_vals[m];
    int s = rowptr[r], e = rowptr[r + 1];
    float4 acc = make_float4(0.f, 0.f, 0.f, 0.f);
    int i = s;
    for (; i + 1 < e; i += 2) {
        int s0 = srcs[i], s1 = srcs[i + 1];
        float v0 = vals[i], v1 = vals[i + 1];
        float4 x0 = *(const float4*)&g_fts[s0 * HH + f];
        float4 x1 = *(const float4*)&g_fts[s1 * HH + f];
        acc.x += v0 * x0.x + v1 * x1.x;
        acc.y += v0 * x0.y + v1 * x1.y;
        acc.z += v0 * x0.z + v1 * x1.z;
        acc.w += v0 * x0.w + v1 * x1.w;
    }
    if (i < e) {
        int s0 = srcs[i]; float v0 = vals[i];
        float4 x0 = *(const float4*)&g_fts[s0 * HH + f];
        acc.x += v0 * x0.x; acc.y += v0 * x0.y;
        acc.z += v0 * x0.z; acc.w += v0 * x0.w;
    }
    float a = slope[0];
    float4 bb = *(const float4*)&bias[f];
    float4 o;
    o.x = acc.x + bb.x; o.x = o.x > 0.f ? o.x : a * o.x;
    o.y = acc.y + bb.y; o.y = o.y > 0.f ? o.y : a * o.y;
    o.z = acc.z + bb.z; o.z = o.z > 0.f ? o.z : a * o.z;
    o.w = acc.w + bb.w; o.w = o.w > 0.f ? o.w : a * o.w;
    *(float4*)&g_embed[obuf][r * HH + f] = o;

    __nv_bfloat16 hi[4], lo[4];
    split4(o, hi, lo);
    *(uint2*)&g_ebh[obuf][r * HH + f] = *(uint2*)hi;
    *(uint2*)&g_ebl[obuf][r * HH + f] = *(uint2*)lo;
}

// ---------------- attention softmax over metapaths ----------------
__global__ void k_beta(const float* __restrict__ att, int side) {
    __shared__ float red[256];
    __shared__ float sres[2];
    int t = threadIdx.x;
    float a = att[t];
    for (int p = 0; p < 2; p++) {
        red[t] = g_sp[side * 2 + p][t] * a;
        __syncthreads();
        for (int off = 128; off > 0; off >>= 1) {
            if (t < off) red[t] += red[t + off];
            __syncthreads();
        }
        if (t == 0) sres[p] = red[0];
        __syncthreads();
    }
    if (t == 0) {
        float s0 = sres[0] / (float)NN, s1 = sres[1] / (float)NN;
        float mx = fmaxf(s0, s1);
        float e0 = expf(s0 - mx), e1 = expf(s1 - mx);
        float inv = 1.f / (e0 + e1);
        g_beta[side * 2 + 0] = e0 * inv;
        g_beta[side * 2 + 1] = e1 * inv;
    }
}

// ---------------- z = beta0*e0 + beta1*e1 ----------------
__global__ void k_combine(int side, float* __restrict__ out) {
    float b0 = g_beta[side * 2], b1 = g_beta[side * 2 + 1];
    const float4* e0 = (const float4*)g_embed[0];
    const float4* e1 = (const float4*)g_embed[1];
    float4* o = (float4*)(out + (size_t)side * NN * HH);
    int tot = NN * HH / 4;
    for (int i = blockIdx.x * blockDim.x + threadIdx.x; i < tot;
         i += gridDim.x * blockDim.x) {
        float4 x = e0[i], y = e1[i];
        o[i] = make_float4(b0 * x.x + b1 * y.x, b0 * x.y + b1 * y.y,
                           b0 * x.z + b1 * y.z, b0 * x.w + b1 * y.w);
    }
}

// ---------------- launch ----------------
extern "C" void kernel_launch(void* const* d_in, const int* in_sizes, int n_in,
                              void* d_out, int out_size) {
    const float* h_side[2] = {(const float*)d_in[0], (const float*)d_in[1]};
    const int*   idx[4] = {(const int*)d_in[2], (const int*)d_in[4],
                           (const int*)d_in[6], (const int*)d_in[8]};
    const float* val[4] = {(const float*)d_in[3], (const float*)d_in[5],
                           (const float*)d_in[7], (const float*)d_in[9]};
    const float* Wm[4] = {(const float*)d_in[10], (const float*)d_in[13],
                          (const float*)d_in[16], (const float*)d_in[19]};
    const float* bm[4] = {(const float*)d_in[11], (const float*)d_in[14],
                          (const float*)d_in[17], (const float*)d_in[20]};
    const float* am[4] = {(const float*)d_in[12], (const float*)d_in[15],
                          (const float*)d_in[18], (const float*)d_in[21]};
    const float* fcW[2] = {(const float*)d_in[22], (const float*)d_in[25]};
    const float* fcb[2] = {(const float*)d_in[23], (const float*)d_in[26]};
    const float* att[2] = {(const float*)d_in[24], (const float*)d_in[27]};
    float* out = (float*)d_out;

    cudaFuncSetAttribute(k_mma<0>, cudaFuncAttributeMaxDynamicSharedMemorySize, SMEM_SZ);
    cudaFuncSetAttribute(k_mma<1>, cudaFuncAttributeMaxDynamicSharedMemorySize, SMEM_SZ);

    k_init<<<784, 256>>>();
    for (int m = 0; m < 4; m++)
        k_hist<<<(EE + 255) / 256, 256>>>(idx[m], m);
    k_scan<<<4, 1024>>>();
    for (int m = 0; m < 4; m++)
        k_scatter<<<(EE + 255) / 256, 256>>>(idx[m], val[m], m);

    for (int m = 0; m < 4; m++) k_convw<<<64, 256>>>(Wm[m], m);
    k_convw<<<64, 256>>>(fcW[0], 4);
    k_convw<<<64, 256>>>(fcW[1], 5);

    dim3 ggrid((NN + 127) / 128, 2);   // 391 x 2
    for (int side = 0; side < 2; side++) {
        k_conva<<<2048, 256>>>(h_side[side]);
        for (int p = 0; p < 2; p++) {
            int m = side * 2 + p;
            k_mma<0><<<ggrid, 256, SMEM_SZ>>>(0, m, nullptr, 0);
            k_spmm<<<(NN + 3) / 4, 256>>>(m, p, bm[m], am[m]);
        }
        for (int p = 0; p < 2; p++) {
            int m = side * 2 + p;
            k_mma<1><<<ggrid, 256, SMEM_SZ>>>(1 + p, 4 + side, fcb[side], m);
        }
        k_beta<<<1, 256>>>(att[side], side);
        k_combine<<<2048, 256>>>(side, out);
    }
}

// round 4
// speedup vs baseline: 1.8325x; 1.0199x over previous
#include <cuda_runtime.h>
#include <cuda_bf16.h>
#include <cstdint>

#define NN 50000
#define HH 256
#define EE 800000

// ---------------- scratch (static device globals; no allocation) ----------------
__device__ int   g_cnt[4][NN];
__device__ int   g_rowptr[4][NN + 1];
__device__ int   g_srcs[4][EE];
__device__ float g_vals[4][EE];
__device__ float g_sp[4][HH];
__device__ float g_beta[4];

// bf16 hi/lo split operands
__device__ __nv_bfloat16 g_aggh[NN * HH], g_aggl[NN * HH];      // SpMM output (GEMM input)
__device__ __nv_bfloat16 g_ebh[2][NN * HH], g_ebl[2][NN * HH];  // embeds (fc input + combine)
__device__ __nv_bfloat16 g_wh[6][HH * HH], g_wl[6][HH * HH];    // weights

struct IdxPtrs { const int* p[4]; };
struct ValPtrs { const float* p[4]; };

// ---------------- helpers ----------------
__device__ __forceinline__ uint32_t smem_u32(const void* p) {
    uint32_t a;
    asm("{ .reg .u64 t; cvta.to.shared.u64 t, %1; cvt.u32.u64 %0, t; }" : "=r"(a) : "l"(p));
    return a;
}
__device__ __forceinline__ void ldsm4(uint32_t* r, uint32_t addr) {
    asm volatile("ldmatrix.sync.aligned.m8n8.x4.shared.b16 {%0,%1,%2,%3}, [%4];"
                 : "=r"(r[0]), "=r"(r[1]), "=r"(r[2]), "=r"(r[3]) : "r"(addr));
}
__device__ __forceinline__ void mma16816(float* c, const uint32_t* a,
                                         uint32_t b0, uint32_t b1) {
    asm volatile(
        "mma.sync.aligned.m16n8k16.row.col.f32.bf16.bf16.f32 "
        "{%0,%1,%2,%3}, {%4,%5,%6,%7}, {%8,%9}, {%0,%1,%2,%3};"
        : "+f"(c[0]), "+f"(c[1]), "+f"(c[2]), "+f"(c[3])
        : "r"(a[0]), "r"(a[1]), "r"(a[2]), "r"(a[3]), "r"(b0), "r"(b1));
}
__device__ __forceinline__ float tanhA(float x) {
    float y;
    asm("tanh.approx.f32 %0, %1;" : "=f"(y) : "f"(x));
    return y;
}
__device__ __forceinline__ void split4(float4 v, __nv_bfloat16* hi, __nv_bfloat16* lo) {
    __nv_bfloat16 h0 = __float2bfloat16(v.x), h1 = __float2bfloat16(v.y);
    __nv_bfloat16 h2 = __float2bfloat16(v.z), h3 = __float2bfloat16(v.w);
    hi[0] = h0; hi[1] = h1; hi[2] = h2; hi[3] = h3;
    lo[0] = __float2bfloat16(v.x - __bfloat162float(h0));
    lo[1] = __float2bfloat16(v.y - __bfloat162float(h1));
    lo[2] = __float2bfloat16(v.z - __bfloat162float(h2));
    lo[3] = __float2bfloat16(v.w - __bfloat162float(h3));
}

// ---------------- CSR build (all 4 paths per launch) ----------------
__global__ void k_hist4(IdxPtrs ip) {
    int m = blockIdx.y;
    int i = blockIdx.x * blockDim.x + threadIdx.x;
    if (i < EE) atomicAdd(&g_cnt[m][ip.p[m][i]], 1);
}

__global__ void k_scan() {
    int m = blockIdx.x;
    int t = threadIdx.x;
    const int PER = (NN + 1023) / 1024;
    int b = t * PER;
    int e = b + PER; if (e > NN) e = NN;
    int s = 0;
    for (int i = b; i < e; i++) s += g_cnt[m][i];
    __shared__ int part[1024];
    part[t] = s;
    __syncthreads();
    for (int off = 1; off < 1024; off <<= 1) {
        int v = (t >= off) ? part[t - off] : 0;
        __syncthreads();
        part[t] += v;
        __syncthreads();
    }
    int run = part[t] - s;
    for (int i = b; i < e; i++) {
        int c = g_cnt[m][i];
        g_rowptr[m][i] = run;
        g_cnt[m][i] = run;
        run += c;
    }
    if (t == 0) g_rowptr[m][NN] = EE;
}

__global__ void k_scatter4(IdxPtrs ip, ValPtrs vp) {
    int m = blockIdx.y;
    int i = blockIdx.x * blockDim.x + threadIdx.x;
    if (i < EE) {
        int d = ip.p[m][i];
        int s = ip.p[m][EE + i];
        int pos = atomicAdd(&g_cnt[m][d], 1);
        g_srcs[m][pos] = s;
        g_vals[m][pos] = vp.p[m][i];
    }
}

// ---------------- weight bf16 hi/lo conversion ----------------
__global__ void k_convw(const float* __restrict__ X, int widx) {
    int tot = HH * HH / 4;
    for (int i = blockIdx.x * blockDim.x + threadIdx.x; i < tot;
         i += gridDim.x * blockDim.x) {
        float4 v = ((const float4*)X)[i];
        __nv_bfloat16 hi[4], lo[4];
        split4(v, hi, lo);
        *(uint2*)&g_wh[widx][i * 4] = *(uint2*)hi;
        *(uint2*)&g_wl[widx][i * 4] = *(uint2*)lo;
    }
}

// ---------------- CSR SpMM on raw h -> bf16 hi/lo aggregate ----------------
__global__ __launch_bounds__(256) void k_spmm(int m, const float* __restrict__ h) {
    int r = blockIdx.x * 4 + (threadIdx.x >> 6);
    int f = (threadIdx.x & 63) << 2;
    if (r >= NN) return;
    const int* __restrict__ srcs = g_srcs[m];
    const float* __restrict__ vals = g_vals[m];
    int s = g_rowptr[m][r], e = g_rowptr[m][r + 1];
    float4 acc = make_float4(0.f, 0.f, 0.f, 0.f);
    int i = s;
    for (; i + 1 < e; i += 2) {
        int s0 = srcs[i], s1 = srcs[i + 1];
        float v0 = vals[i], v1 = vals[i + 1];
        float4 x0 = *(const float4*)&h[s0 * HH + f];
        float4 x1 = *(const float4*)&h[s1 * HH + f];
        acc.x += v0 * x0.x + v1 * x1.x;
        acc.y += v0 * x0.y + v1 * x1.y;
        acc.z += v0 * x0.z + v1 * x1.z;
        acc.w += v0 * x0.w + v1 * x1.w;
    }
    if (i < e) {
        int s0 = srcs[i]; float v0 = vals[i];
        float4 x0 = *(const float4*)&h[s0 * HH + f];
        acc.x += v0 * x0.x; acc.y += v0 * x0.y;
        acc.z += v0 * x0.z; acc.w += v0 * x0.w;
    }
    __nv_bfloat16 hi[4], lo[4];
    split4(acc, hi, lo);
    *(uint2*)&g_aggh[r * HH + f] = *(uint2*)hi;
    *(uint2*)&g_aggl[r * HH + f] = *(uint2*)lo;
}

// ---------------- HMMA GEMM: C = A @ W^T (bf16 hi/lo 3-pass, fp32 accum) ----------------
// CTA tile 128x128, 8 warps, K chunks of 64.
// MODE 2 (GCN): PReLU(C + bias) -> g_ebh/g_ebl[obuf]  (bf16 hi/lo)
// MODE 1 (fc):  colsum of tanh(C + bias) -> g_sp[spIdx]
#define ASTRIDE 72
#define TILE_E (128 * ASTRIDE)
#define SMEM_SZ (4 * TILE_E * 2 + 512)

template <int MODE>
__global__ __launch_bounds__(256) void k_mma(int asel, int widx,
                                             const float* __restrict__ bias,
                                             const float* __restrict__ slope,
                                             int spIdx, int obuf) {
    extern __shared__ char smraw[];
    __nv_bfloat16* sAh = (__nv_bfloat16*)smraw;
    __nv_bfloat16* sAl = sAh + TILE_E;
    __nv_bfloat16* sBh = sAl + TILE_E;
    __nv_bfloat16* sBl = sBh + TILE_E;
    float* red = (float*)(sBl + TILE_E);

    const __nv_bfloat16 *Ah, *Al;
    if (asel < 0) { Ah = g_aggh; Al = g_aggl; }
    else          { Ah = g_ebh[asel]; Al = g_ebl[asel]; }
    const __nv_bfloat16* Bh = g_wh[widx];
    const __nv_bfloat16* Bl = g_wl[widx];

    int tid = threadIdx.x, lane = tid & 31, wid = tid >> 5;
    int warp_m = wid & 3, warp_n = wid >> 2;
    int rowBase = blockIdx.x * 128;
    int colBase = blockIdx.y * 128;

    uint32_t sb = smem_u32(smraw);
    uint32_t uAh = sb, uAl = sb + TILE_E * 2, uBh = sb + 2 * TILE_E * 2,
             uBl = sb + 3 * TILE_E * 2;

    float acc[2][8][4];
#pragma unroll
    for (int i = 0; i < 2; i++)
#pragma unroll
        for (int j = 0; j < 8; j++)
#pragma unroll
            for (int q = 0; q < 4; q++) acc[i][j][q] = 0.f;

    for (int kb = 0; kb < 4; kb++) {
        if (kb) __syncthreads();
#pragma unroll
        for (int l = 0; l < 4; l++) {
            int idx = tid + l * 256;
            int r = idx >> 3, c = (idx & 7) * 8;
            int so = r * ASTRIDE + c;
            int gr = rowBase + r;
            uint4 vh = make_uint4(0, 0, 0, 0), vl = make_uint4(0, 0, 0, 0);
            if (gr < NN) {
                vh = *(const uint4*)&Ah[gr * HH + kb * 64 + c];
                vl = *(const uint4*)&Al[gr * HH + kb * 64 + c];
            }
            *(uint4*)&sAh[so] = vh;
            *(uint4*)&sAl[so] = vl;
            int gb = (colBase + r) * HH + kb * 64 + c;
            *(uint4*)&sBh[so] = *(const uint4*)&Bh[gb];
            *(uint4*)&sBl[so] = *(const uint4*)&Bl[gb];
        }
        __syncthreads();

#pragma unroll
        for (int ks = 0; ks < 4; ks++) {
            uint32_t ah[2][4], al[2][4], bh[4][4], bl[4][4];
            uint32_t lrow = (uint32_t)(lane & 15);
            uint32_t lcol = (uint32_t)((lane >> 4) * 8 + ks * 16);
#pragma unroll
            for (int mt = 0; mt < 2; mt++) {
                uint32_t off = ((warp_m * 32 + mt * 16 + lrow) * ASTRIDE + lcol) * 2;
                ldsm4(ah[mt], uAh + off);
                ldsm4(al[mt], uAl + off);
            }
#pragma unroll
            for (int nt = 0; nt < 4; nt++) {
                uint32_t off = ((warp_n * 64 + nt * 16 + lrow) * ASTRIDE + lcol) * 2;
                ldsm4(bh[nt], uBh + off);
                ldsm4(bl[nt], uBl + off);
            }
#pragma unroll
            for (int mt = 0; mt < 2; mt++)
#pragma unroll
                for (int nt = 0; nt < 4; nt++)
#pragma unroll
                    for (int h = 0; h < 2; h++) {
                        float* c = acc[mt][nt * 2 + h];
                        mma16816(c, ah[mt], bh[nt][h], bh[nt][h + 2]);  // hi*hi
                        mma16816(c, ah[mt], bl[nt][h], bl[nt][h + 2]);  // hi*lo
                        mma16816(c, al[mt], bh[nt][h], bh[nt][h + 2]);  // lo*hi
                    }
        }
    }

    // ---------------- epilogue ----------------
    if (MODE == 2) {
        float sl = slope[0];
#pragma unroll
        for (int mt = 0; mt < 2; mt++) {
            int row0 = rowBase + warp_m * 32 + mt * 16 + (lane >> 2);
#pragma unroll
            for (int n = 0; n < 8; n++) {
                int col = colBase + warp_n * 64 + (n >> 1) * 16 + (n & 1) * 8 +
                          (lane & 3) * 2;
                float b0 = bias[col], b1 = bias[col + 1];
                float* c = acc[mt][n];
#pragma unroll
                for (int half = 0; half < 2; half++) {
                    int row = row0 + half * 8;
                    if (row < NN) {
                        float v0 = c[half * 2 + 0] + b0;
                        float v1 = c[half * 2 + 1] + b1;
                        v0 = v0 > 0.f ? v0 : sl * v0;
                        v1 = v1 > 0.f ? v1 : sl * v1;
                        __nv_bfloat16 h0 = __float2bfloat16(v0);
                        __nv_bfloat16 h1 = __float2bfloat16(v1);
                        __nv_bfloat162 hp; hp.x = h0; hp.y = h1;
                        __nv_bfloat162 lp;
                        lp.x = __float2bfloat16(v0 - __bfloat162float(h0));
                        lp.y = __float2bfloat16(v1 - __bfloat162float(h1));
                        *(__nv_bfloat162*)&g_ebh[obuf][row * HH + col] = hp;
                        *(__nv_bfloat162*)&g_ebl[obuf][row * HH + col] = lp;
                    }
                }
            }
        }
    } else {
        for (int i = tid; i < 128; i += 256) red[i] = 0.f;
        __syncthreads();
#pragma unroll
        for (int n = 0; n < 8; n++) {
            int lcol = warp_n * 64 + (n >> 1) * 16 + (n & 1) * 8 + (lane & 3) * 2;
            float b0 = bias[colBase + lcol], b1 = bias[colBase + lcol + 1];
            float s0 = 0.f, s1 = 0.f;
#pragma unroll
            for (int mt = 0; mt < 2; mt++) {
                int row0 = rowBase + warp_m * 32 + mt * 16 + (lane >> 2);
                float* c = acc[mt][n];
                if (row0 < NN)     { s0 += tanhA(c[0] + b0); s1 += tanhA(c[1] + b1); }
                if (row0 + 8 < NN) { s0 += tanhA(c[2] + b0); s1 += tanhA(c[3] + b1); }
            }
            s0 += __shfl_xor_sync(0xffffffffu, s0, 4);
            s0 += __shfl_xor_sync(0xffffffffu, s0, 8);
            s0 += __shfl_xor_sync(0xffffffffu, s0, 16);
            s1 += __shfl_xor_sync(0xffffffffu, s1, 4);
            s1 += __shfl_xor_sync(0xffffffffu, s1, 8);
            s1 += __shfl_xor_sync(0xffffffffu, s1, 16);
            if (lane < 4) {
                int c0 = warp_n * 64 + (n >> 1) * 16 + (n & 1) * 8 + lane * 2;
                atomicAdd(&red[c0], s0);
                atomicAdd(&red[c0 + 1], s1);
            }
        }
        __syncthreads();
        if (tid < 128) atomicAdd(&g_sp[spIdx][colBase + tid], red[tid]);
    }
}

// ---------------- attention softmax over metapaths ----------------
__global__ void k_beta(const float* __restrict__ att, int side) {
    __shared__ float red[256];
    __shared__ float sres[2];
    int t = threadIdx.x;
    float a = att[t];
    for (int p = 0; p < 2; p++) {
        red[t] = g_sp[side * 2 + p][t] * a;
        __syncthreads();
        for (int off = 128; off > 0; off >>= 1) {
            if (t < off) red[t] += red[t + off];
            __syncthreads();
        }
        if (t == 0) sres[p] = red[0];
        __syncthreads();
    }
    if (t == 0) {
        float s0 = sres[0] / (float)NN, s1 = sres[1] / (float)NN;
        float mx = fmaxf(s0, s1);
        float e0 = expf(s0 - mx), e1 = expf(s1 - mx);
        float inv = 1.f / (e0 + e1);
        g_beta[side * 2 + 0] = e0 * inv;
        g_beta[side * 2 + 1] = e1 * inv;
    }
}

// ---------------- z = beta0*(h0+l0) + beta1*(h1+l1) ----------------
__global__ void k_combine(int side, float* __restrict__ out) {
    float b0 = g_beta[side * 2], b1 = g_beta[side * 2 + 1];
    const uint2* h0p = (const uint2*)g_ebh[0];
    const uint2* l0p = (const uint2*)g_ebl[0];
    const uint2* h1p = (const uint2*)g_ebh[1];
    const uint2* l1p = (const uint2*)g_ebl[1];
    float4* o = (float4*)(out + (size_t)side * NN * HH);
    int tot = NN * HH / 4;
    for (int i = blockIdx.x * blockDim.x + threadIdx.x; i < tot;
         i += gridDim.x * blockDim.x) {
        uint2 h0 = h0p[i], l0 = l0p[i], h1 = h1p[i], l1 = l1p[i];
        const __nv_bfloat162* H0 = (const __nv_bfloat162*)&h0;
        const __nv_bfloat162* L0 = (const __nv_bfloat162*)&l0;
        const __nv_bfloat162* H1 = (const __nv_bfloat162*)&h1;
        const __nv_bfloat162* L1 = (const __nv_bfloat162*)&l1;
        float4 r;
        r.x = b0 * (__bfloat162float(H0[0].x) + __bfloat162float(L0[0].x))
            + b1 * (__bfloat162float(H1[0].x) + __bfloat162float(L1[0].x));
        r.y = b0 * (__bfloat162float(H0[0].y) + __bfloat162float(L0[0].y))
            + b1 * (__bfloat162float(H1[0].y) + __bfloat162float(L1[0].y));
        r.z = b0 * (__bfloat162float(H0[1].x) + __bfloat162float(L0[1].x))
            + b1 * (__bfloat162float(H1[1].x) + __bfloat162float(L1[1].x));
        r.w = b0 * (__bfloat162float(H0[1].y) + __bfloat162float(L0[1].y))
            + b1 * (__bfloat162float(H1[1].y) + __bfloat162float(L1[1].y));
        o[i] = r;
    }
}

// ---------------- launch ----------------
extern "C" void kernel_launch(void* const* d_in, const int* in_sizes, int n_in,
                              void* d_out, int out_size) {
    const float* h_side[2] = {(const float*)d_in[0], (const float*)d_in[1]};
    IdxPtrs ip; ValPtrs vp;
    ip.p[0] = (const int*)d_in[2]; vp.p[0] = (const float*)d_in[3];
    ip.p[1] = (const int*)d_in[4]; vp.p[1] = (const float*)d_in[5];
    ip.p[2] = (const int*)d_in[6]; vp.p[2] = (const float*)d_in[7];
    ip.p[3] = (const int*)d_in[8]; vp.p[3] = (const float*)d_in[9];
    const float* Wm[4] = {(const float*)d_in[10], (const float*)d_in[13],
                          (const float*)d_in[16], (const float*)d_in[19]};
    const float* bm[4] = {(const float*)d_in[11], (const float*)d_in[14],
                          (const float*)d_in[17], (const float*)d_in[20]};
    const float* am[4] = {(const float*)d_in[12], (const float*)d_in[15],
                          (const float*)d_in[18], (const float*)d_in[21]};
    const float* fcW[2] = {(const float*)d_in[22], (const float*)d_in[25]};
    const float* fcb[2] = {(const float*)d_in[23], (const float*)d_in[26]};
    const float* att[2] = {(const float*)d_in[24], (const float*)d_in[27]};
    float* out = (float*)d_out;

    cudaFuncSetAttribute(k_mma<1>, cudaFuncAttributeMaxDynamicSharedMemorySize, SMEM_SZ);
    cudaFuncSetAttribute(k_mma<2>, cudaFuncAttributeMaxDynamicSharedMemorySize, SMEM_SZ);

    void* cntAddr = nullptr; cudaGetSymbolAddress(&cntAddr, g_cnt);
    void* spAddr = nullptr;  cudaGetSymbolAddress(&spAddr, g_sp);
    cudaMemsetAsync(cntAddr, 0, sizeof(int) * 4 * NN);
    cudaMemsetAsync(spAddr, 0, sizeof(float) * 4 * HH);

    dim3 eg((EE + 255) / 256, 4);
    k_hist4<<<eg, 256>>>(ip);
    k_scan<<<4, 1024>>>();
    k_scatter4<<<eg, 256>>>(ip, vp);

    for (int m = 0; m < 4; m++) k_convw<<<64, 256>>>(Wm[m], m);
    k_convw<<<64, 256>>>(fcW[0], 4);
    k_convw<<<64, 256>>>(fcW[1], 5);

    dim3 ggrid((NN + 127) / 128, 2);   // 391 x 2
    for (int side = 0; side < 2; side++) {
        for (int p = 0; p < 2; p++) {
            int m = side * 2 + p;
            k_spmm<<<(NN + 3) / 4, 256>>>(m, h_side[side]);
            k_mma<2><<<ggrid, 256, SMEM_SZ>>>(-1, m, bm[m], am[m], 0, p);
        }
        for (int p = 0; p < 2; p++) {
            int m = side * 2 + p;
            k_mma<1><<<ggrid, 256, SMEM_SZ>>>(p, 4 + side, fcb[side], nullptr, m, 0);
        }
        k_beta<<<1, 256>>>(att[side], side);
        k_combine<<<2048, 256>>>(side, out);
    }
}

// round 5
// speedup vs baseline: 2.3662x; 1.2912x over previous
#include <cuda_runtime.h>
#include <cuda_bf16.h>
#include <cstdint>

#define NN 50000
#define HH 256
#define EE 800000

// ---------------- scratch (static device globals; no allocation) ----------------
__device__ int   g_cnt[4][NN];
__device__ int   g_rowptr[4][NN + 1];
__device__ int   g_srcs[4][EE];
__device__ float g_vals[4][EE];
__device__ float g_sp[4][HH];
__device__ float g_beta[4];

// bf16 hi/lo split operands
__device__ __nv_bfloat16 g_aggh[4][NN * HH], g_aggl[4][NN * HH]; // SpMM out (GEMM in)
__device__ __nv_bfloat16 g_ebh[4][NN * HH], g_ebl[4][NN * HH];   // embeds
__device__ __nv_bfloat16 g_wh[6][HH * HH], g_wl[6][HH * HH];     // weights

struct IdxPtrs { const int* p[4]; };
struct ValPtrs { const float* p[4]; };
struct W6Ptrs  { const float* p[6]; };
struct GcnPar  { const float* bias[4]; const float* slope[4]; };
struct FcPar   { const float* fcb[2]; };

// ---------------- helpers ----------------
__device__ __forceinline__ uint32_t smem_u32(const void* p) {
    uint32_t a;
    asm("{ .reg .u64 t; cvta.to.shared.u64 t, %1; cvt.u32.u64 %0, t; }" : "=r"(a) : "l"(p));
    return a;
}
__device__ __forceinline__ void ldsm4(uint32_t* r, uint32_t addr) {
    asm volatile("ldmatrix.sync.aligned.m8n8.x4.shared.b16 {%0,%1,%2,%3}, [%4];"
                 : "=r"(r[0]), "=r"(r[1]), "=r"(r[2]), "=r"(r[3]) : "r"(addr));
}
__device__ __forceinline__ void mma16816(float* c, const uint32_t* a,
                                         uint32_t b0, uint32_t b1) {
    asm volatile(
        "mma.sync.aligned.m16n8k16.row.col.f32.bf16.bf16.f32 "
        "{%0,%1,%2,%3}, {%4,%5,%6,%7}, {%8,%9}, {%0,%1,%2,%3};"
        : "+f"(c[0]), "+f"(c[1]), "+f"(c[2]), "+f"(c[3])
        : "r"(a[0]), "r"(a[1]), "r"(a[2]), "r"(a[3]), "r"(b0), "r"(b1));
}
__device__ __forceinline__ float tanhA(float x) {
    float y;
    asm("tanh.approx.f32 %0, %1;" : "=f"(y) : "f"(x));
    return y;
}
__device__ __forceinline__ void split4(float4 v, __nv_bfloat16* hi, __nv_bfloat16* lo) {
    __nv_bfloat16 h0 = __float2bfloat16(v.x), h1 = __float2bfloat16(v.y);
    __nv_bfloat16 h2 = __float2bfloat16(v.z), h3 = __float2bfloat16(v.w);
    hi[0] = h0; hi[1] = h1; hi[2] = h2; hi[3] = h3;
    lo[0] = __float2bfloat16(v.x - __bfloat162float(h0));
    lo[1] = __float2bfloat16(v.y - __bfloat162float(h1));
    lo[2] = __float2bfloat16(v.z - __bfloat162float(h2));
    lo[3] = __float2bfloat16(v.w - __bfloat162float(h3));
}

// ---------------- CSR build (all 4 paths per launch) ----------------
__global__ void k_hist4(IdxPtrs ip) {
    int m = blockIdx.y;
    int i = blockIdx.x * blockDim.x + threadIdx.x;
    if (i < EE) atomicAdd(&g_cnt[m][ip.p[m][i]], 1);
}

__global__ void k_scan() {
    int m = blockIdx.x;
    int t = threadIdx.x;
    const int PER = (NN + 1023) / 1024;
    int b = t * PER;
    int e = b + PER; if (e > NN) e = NN;
    int s = 0;
    for (int i = b; i < e; i++) s += g_cnt[m][i];
    __shared__ int part[1024];
    part[t] = s;
    __syncthreads();
    for (int off = 1; off < 1024; off <<= 1) {
        int v = (t >= off) ? part[t - off] : 0;
        __syncthreads();
        part[t] += v;
        __syncthreads();
    }
    int run = part[t] - s;
    for (int i = b; i < e; i++) {
        int c = g_cnt[m][i];
        g_rowptr[m][i] = run;
        g_cnt[m][i] = run;
        run += c;
    }
    if (t == 0) g_rowptr[m][NN] = EE;
}

__global__ void k_scatter4(IdxPtrs ip, ValPtrs vp) {
    int m = blockIdx.y;
    int i = blockIdx.x * blockDim.x + threadIdx.x;
    if (i < EE) {
        int d = ip.p[m][i];
        int s = ip.p[m][EE + i];
        int pos = atomicAdd(&g_cnt[m][d], 1);
        g_srcs[m][pos] = s;
        g_vals[m][pos] = vp.p[m][i];
    }
}

// ---------------- weight bf16 hi/lo conversion (6 weights, one launch) ----------------
__global__ void k_convw6(W6Ptrs w) {
    int widx = blockIdx.y;
    const float* X = w.p[widx];
    int tot = HH * HH / 4;
    for (int i = blockIdx.x * blockDim.x + threadIdx.x; i < tot;
         i += gridDim.x * blockDim.x) {
        float4 v = ((const float4*)X)[i];
        __nv_bfloat16 hi[4], lo[4];
        split4(v, hi, lo);
        *(uint2*)&g_wh[widx][i * 4] = *(uint2*)hi;
        *(uint2*)&g_wl[widx][i * 4] = *(uint2*)lo;
    }
}

// ---------------- CSR SpMM on raw h -> bf16 hi/lo aggregate (4 paths, one launch) ----
__global__ __launch_bounds__(256) void k_spmm4(const float* __restrict__ h_d,
                                               const float* __restrict__ h_p) {
    int m = blockIdx.y;
    const float* __restrict__ h = (m < 2) ? h_d : h_p;
    int r = blockIdx.x * 4 + (threadIdx.x >> 6);
    int f = (threadIdx.x & 63) << 2;
    if (r >= NN) return;
    const int* __restrict__ srcs = g_srcs[m];
    const float* __restrict__ vals = g_vals[m];
    int s = g_rowptr[m][r], e = g_rowptr[m][r + 1];
    float4 acc = make_float4(0.f, 0.f, 0.f, 0.f);
    int i = s;
    for (; i + 1 < e; i += 2) {
        int s0 = srcs[i], s1 = srcs[i + 1];
        float v0 = vals[i], v1 = vals[i + 1];
        float4 x0 = *(const float4*)&h[s0 * HH + f];
        float4 x1 = *(const float4*)&h[s1 * HH + f];
        acc.x += v0 * x0.x + v1 * x1.x;
        acc.y += v0 * x0.y + v1 * x1.y;
        acc.z += v0 * x0.z + v1 * x1.z;
        acc.w += v0 * x0.w + v1 * x1.w;
    }
    if (i < e) {
        int s0 = srcs[i]; float v0 = vals[i];
        float4 x0 = *(const float4*)&h[s0 * HH + f];
        acc.x += v0 * x0.x; acc.y += v0 * x0.y;
        acc.z += v0 * x0.z; acc.w += v0 * x0.w;
    }
    __nv_bfloat16 hi[4], lo[4];
    split4(acc, hi, lo);
    *(uint2*)&g_aggh[m][r * HH + f] = *(uint2*)hi;
    *(uint2*)&g_aggl[m][r * HH + f] = *(uint2*)lo;
}

// ---------------- GCN GEMM (3-pass hi/lo): PReLU(agg@W^T + b) -> eb hi/lo ----------
#define ASTRIDE 72
#define TILE_E (128 * ASTRIDE)
#define SMEM_G (4 * TILE_E * 2)           // 4 tiles
#define SMEM_F (2 * TILE_E * 2 + 512)     // 2 tiles + red

__global__ __launch_bounds__(256, 2) void k_gcnmma(GcnPar gp) {
    extern __shared__ char smraw[];
    __nv_bfloat16* sAh = (__nv_bfloat16*)smraw;
    __nv_bfloat16* sAl = sAh + TILE_E;
    __nv_bfloat16* sBh = sAl + TILE_E;
    __nv_bfloat16* sBl = sBh + TILE_E;

    int m = blockIdx.z;
    const __nv_bfloat16* Ah = g_aggh[m];
    const __nv_bfloat16* Al = g_aggl[m];
    const __nv_bfloat16* Bh = g_wh[m];
    const __nv_bfloat16* Bl = g_wl[m];
    const float* bias = gp.bias[m];

    int tid = threadIdx.x, lane = tid & 31, wid = tid >> 5;
    int warp_m = wid & 3, warp_n = wid >> 2;
    int rowBase = blockIdx.x * 128;
    int colBase = blockIdx.y * 128;

    uint32_t sb = smem_u32(smraw);
    uint32_t uAh = sb, uAl = sb + TILE_E * 2, uBh = sb + 2 * TILE_E * 2,
             uBl = sb + 3 * TILE_E * 2;

    float acc[2][8][4];
#pragma unroll
    for (int i = 0; i < 2; i++)
#pragma unroll
        for (int j = 0; j < 8; j++)
#pragma unroll
            for (int q = 0; q < 4; q++) acc[i][j][q] = 0.f;

    for (int kb = 0; kb < 4; kb++) {
        if (kb) __syncthreads();
#pragma unroll
        for (int l = 0; l < 4; l++) {
            int idx = tid + l * 256;
            int r = idx >> 3, c = (idx & 7) * 8;
            int so = r * ASTRIDE + c;
            int gr = rowBase + r;
            uint4 vh = make_uint4(0, 0, 0, 0), vl = make_uint4(0, 0, 0, 0);
            if (gr < NN) {
                vh = *(const uint4*)&Ah[gr * HH + kb * 64 + c];
                vl = *(const uint4*)&Al[gr * HH + kb * 64 + c];
            }
            *(uint4*)&sAh[so] = vh;
            *(uint4*)&sAl[so] = vl;
            int gb = (colBase + r) * HH + kb * 64 + c;
            *(uint4*)&sBh[so] = *(const uint4*)&Bh[gb];
            *(uint4*)&sBl[so] = *(const uint4*)&Bl[gb];
        }
        __syncthreads();

#pragma unroll
        for (int ks = 0; ks < 4; ks++) {
            uint32_t ah[2][4], al[2][4], bh[4][4], bl[4][4];
            uint32_t lrow = (uint32_t)(lane & 15);
            uint32_t lcol = (uint32_t)((lane >> 4) * 8 + ks * 16);
#pragma unroll
            for (int mt = 0; mt < 2; mt++) {
                uint32_t off = ((warp_m * 32 + mt * 16 + lrow) * ASTRIDE + lcol) * 2;
                ldsm4(ah[mt], uAh + off);
                ldsm4(al[mt], uAl + off);
            }
#pragma unroll
            for (int nt = 0; nt < 4; nt++) {
                uint32_t off = ((warp_n * 64 + nt * 16 + lrow) * ASTRIDE + lcol) * 2;
                ldsm4(bh[nt], uBh + off);
                ldsm4(bl[nt], uBl + off);
            }
#pragma unroll
            for (int mt = 0; mt < 2; mt++)
#pragma unroll
                for (int nt = 0; nt < 4; nt++)
#pragma unroll
                    for (int h = 0; h < 2; h++) {
                        float* c = acc[mt][nt * 2 + h];
                        mma16816(c, ah[mt], bh[nt][h], bh[nt][h + 2]);
                        mma16816(c, ah[mt], bl[nt][h], bl[nt][h + 2]);
                        mma16816(c, al[mt], bh[nt][h], bh[nt][h + 2]);
                    }
        }
    }

    float sl = gp.slope[m][0];
#pragma unroll
    for (int mt = 0; mt < 2; mt++) {
        int row0 = rowBase + warp_m * 32 + mt * 16 + (lane >> 2);
#pragma unroll
        for (int n = 0; n < 8; n++) {
            int col = colBase + warp_n * 64 + (n >> 1) * 16 + (n & 1) * 8 +
                      (lane & 3) * 2;
            float b0 = bias[col], b1 = bias[col + 1];
            float* c = acc[mt][n];
#pragma unroll
            for (int half = 0; half < 2; half++) {
                int row = row0 + half * 8;
                if (row < NN) {
                    float v0 = c[half * 2 + 0] + b0;
                    float v1 = c[half * 2 + 1] + b1;
                    v0 = v0 > 0.f ? v0 : sl * v0;
                    v1 = v1 > 0.f ? v1 : sl * v1;
                    __nv_bfloat16 h0 = __float2bfloat16(v0);
                    __nv_bfloat16 h1 = __float2bfloat16(v1);
                    __nv_bfloat162 hp; hp.x = h0; hp.y = h1;
                    __nv_bfloat162 lp;
                    lp.x = __float2bfloat16(v0 - __bfloat162float(h0));
                    lp.y = __float2bfloat16(v1 - __bfloat162float(h1));
                    *(__nv_bfloat162*)&g_ebh[m][row * HH + col] = hp;
                    *(__nv_bfloat162*)&g_ebl[m][row * HH + col] = lp;
                }
            }
        }
    }
}

// ---------------- fc GEMM (1-pass bf16) + tanh + colsum -> g_sp[m] ----------------
__global__ __launch_bounds__(256, 2) void k_fcmma(FcPar fp) {
    extern __shared__ char smraw[];
    __nv_bfloat16* sAh = (__nv_bfloat16*)smraw;
    __nv_bfloat16* sBh = sAh + TILE_E;
    float* red = (float*)(sBh + TILE_E);

    int m = blockIdx.z;
    int side = m >> 1;
    const __nv_bfloat16* Ah = g_ebh[m];
    const __nv_bfloat16* Bh = g_wh[4 + side];
    const float* bias = fp.fcb[side];

    int tid = threadIdx.x, lane = tid & 31, wid = tid >> 5;
    int warp_m = wid & 3, warp_n = wid >> 2;
    int rowBase = blockIdx.x * 128;
    int colBase = blockIdx.y * 128;

    uint32_t sb = smem_u32(smraw);
    uint32_t uAh = sb, uBh = sb + TILE_E * 2;

    float acc[2][8][4];
#pragma unroll
    for (int i = 0; i < 2; i++)
#pragma unroll
        for (int j = 0; j < 8; j++)
#pragma unroll
            for (int q = 0; q < 4; q++) acc[i][j][q] = 0.f;

    for (int kb = 0; kb < 4; kb++) {
        if (kb) __syncthreads();
#pragma unroll
        for (int l = 0; l < 4; l++) {
            int idx = tid + l * 256;
            int r = idx >> 3, c = (idx & 7) * 8;
            int so = r * ASTRIDE + c;
            int gr = rowBase + r;
            uint4 vh = make_uint4(0, 0, 0, 0);
            if (gr < NN) vh = *(const uint4*)&Ah[gr * HH + kb * 64 + c];
            *(uint4*)&sAh[so] = vh;
            int gb = (colBase + r) * HH + kb * 64 + c;
            *(uint4*)&sBh[so] = *(const uint4*)&Bh[gb];
        }
        __syncthreads();

#pragma unroll
        for (int ks = 0; ks < 4; ks++) {
            uint32_t ah[2][4], bh[4][4];
            uint32_t lrow = (uint32_t)(lane & 15);
            uint32_t lcol = (uint32_t)((lane >> 4) * 8 + ks * 16);
#pragma unroll
            for (int mt = 0; mt < 2; mt++) {
                uint32_t off = ((warp_m * 32 + mt * 16 + lrow) * ASTRIDE + lcol) * 2;
                ldsm4(ah[mt], uAh + off);
            }
#pragma unroll
            for (int nt = 0; nt < 4; nt++) {
                uint32_t off = ((warp_n * 64 + nt * 16 + lrow) * ASTRIDE + lcol) * 2;
                ldsm4(bh[nt], uBh + off);
            }
#pragma unroll
            for (int mt = 0; mt < 2; mt++)
#pragma unroll
                for (int nt = 0; nt < 4; nt++)
#pragma unroll
                    for (int h = 0; h < 2; h++)
                        mma16816(acc[mt][nt * 2 + h], ah[mt], bh[nt][h], bh[nt][h + 2]);
        }
    }

    for (int i = tid; i < 128; i += 256) red[i] = 0.f;
    __syncthreads();
#pragma unroll
    for (int n = 0; n < 8; n++) {
        int lcol = warp_n * 64 + (n >> 1) * 16 + (n & 1) * 8 + (lane & 3) * 2;
        float b0 = bias[colBase + lcol], b1 = bias[colBase + lcol + 1];
        float s0 = 0.f, s1 = 0.f;
#pragma unroll
        for (int mt = 0; mt < 2; mt++) {
            int row0 = rowBase + warp_m * 32 + mt * 16 + (lane >> 2);
            float* c = acc[mt][n];
            if (row0 < NN)     { s0 += tanhA(c[0] + b0); s1 += tanhA(c[1] + b1); }
            if (row0 + 8 < NN) { s0 += tanhA(c[2] + b0); s1 += tanhA(c[3] + b1); }
        }
        s0 += __shfl_xor_sync(0xffffffffu, s0, 4);
        s0 += __shfl_xor_sync(0xffffffffu, s0, 8);
        s0 += __shfl_xor_sync(0xffffffffu, s0, 16);
        s1 += __shfl_xor_sync(0xffffffffu, s1, 4);
        s1 += __shfl_xor_sync(0xffffffffu, s1, 8);
        s1 += __shfl_xor_sync(0xffffffffu, s1, 16);
        if (lane < 4) {
            int c0 = warp_n * 64 + (n >> 1) * 16 + (n & 1) * 8 + lane * 2;
            atomicAdd(&red[c0], s0);
            atomicAdd(&red[c0 + 1], s1);
        }
    }
    __syncthreads();
    if (tid < 128) atomicAdd(&g_sp[m][colBase + tid], red[tid]);
}

// ---------------- attention softmax (both sides, one launch) ----------------
__global__ void k_beta2(const float* __restrict__ attd,
                        const float* __restrict__ attp) {
    __shared__ float red[256];
    __shared__ float sres[2];
    int side = blockIdx.x;
    const float* att = side ? attp : attd;
    int t = threadIdx.x;
    float a = att[t];
    for (int p = 0; p < 2; p++) {
        red[t] = g_sp[side * 2 + p][t] * a;
        __syncthreads();
        for (int off = 128; off > 0; off >>= 1) {
            if (t < off) red[t] += red[t + off];
            __syncthreads();
        }
        if (t == 0) sres[p] = red[0];
        __syncthreads();
    }
    if (t == 0) {
        float s0 = sres[0] / (float)NN, s1 = sres[1] / (float)NN;
        float mx = fmaxf(s0, s1);
        float e0 = expf(s0 - mx), e1 = expf(s1 - mx);
        float inv = 1.f / (e0 + e1);
        g_beta[side * 2 + 0] = e0 * inv;
        g_beta[side * 2 + 1] = e1 * inv;
    }
}

// ---------------- z = beta0*(h0+l0) + beta1*(h1+l1)  (both sides) ----------------
__global__ void k_combine2(float* __restrict__ out) {
    int side = blockIdx.y;
    float b0 = g_beta[side * 2], b1 = g_beta[side * 2 + 1];
    const uint2* h0p = (const uint2*)g_ebh[side * 2];
    const uint2* l0p = (const uint2*)g_ebl[side * 2];
    const uint2* h1p = (const uint2*)g_ebh[side * 2 + 1];
    const uint2* l1p = (const uint2*)g_ebl[side * 2 + 1];
    float4* o = (float4*)(out + (size_t)side * NN * HH);
    int tot = NN * HH / 4;
    for (int i = blockIdx.x * blockDim.x + threadIdx.x; i < tot;
         i += gridDim.x * blockDim.x) {
        uint2 h0 = h0p[i], l0 = l0p[i], h1 = h1p[i], l1 = l1p[i];
        const __nv_bfloat162* H0 = (const __nv_bfloat162*)&h0;
        const __nv_bfloat162* L0 = (const __nv_bfloat162*)&l0;
        const __nv_bfloat162* H1 = (const __nv_bfloat162*)&h1;
        const __nv_bfloat162* L1 = (const __nv_bfloat162*)&l1;
        float4 r;
        r.x = b0 * (__bfloat162float(H0[0].x) + __bfloat162float(L0[0].x))
            + b1 * (__bfloat162float(H1[0].x) + __bfloat162float(L1[0].x));
        r.y = b0 * (__bfloat162float(H0[0].y) + __bfloat162float(L0[0].y))
            + b1 * (__bfloat162float(H1[0].y) + __bfloat162float(L1[0].y));
        r.z = b0 * (__bfloat162float(H0[1].x) + __bfloat162float(L0[1].x))
            + b1 * (__bfloat162float(H1[1].x) + __bfloat162float(L1[1].x));
        r.w = b0 * (__bfloat162float(H0[1].y) + __bfloat162float(L0[1].y))
            + b1 * (__bfloat162float(H1[1].y) + __bfloat162float(L1[1].y));
        o[i] = r;
    }
}

// ---------------- launch ----------------
extern "C" void kernel_launch(void* const* d_in, const int* in_sizes, int n_in,
                              void* d_out, int out_size) {
    const float* h_d = (const float*)d_in[0];
    const float* h_p = (const float*)d_in[1];
    IdxPtrs ip; ValPtrs vp;
    ip.p[0] = (const int*)d_in[2]; vp.p[0] = (const float*)d_in[3];
    ip.p[1] = (const int*)d_in[4]; vp.p[1] = (const float*)d_in[5];
    ip.p[2] = (const int*)d_in[6]; vp.p[2] = (const float*)d_in[7];
    ip.p[3] = (const int*)d_in[8]; vp.p[3] = (const float*)d_in[9];
    W6Ptrs w6;
    w6.p[0] = (const float*)d_in[10]; w6.p[1] = (const float*)d_in[13];
    w6.p[2] = (const float*)d_in[16]; w6.p[3] = (const float*)d_in[19];
    w6.p[4] = (const float*)d_in[22]; w6.p[5] = (const float*)d_in[25];
    GcnPar gp;
    gp.bias[0] = (const float*)d_in[11]; gp.slope[0] = (const float*)d_in[12];
    gp.bias[1] = (const float*)d_in[14]; gp.slope[1] = (const float*)d_in[15];
    gp.bias[2] = (const float*)d_in[17]; gp.slope[2] = (const float*)d_in[18];
    gp.bias[3] = (const float*)d_in[20]; gp.slope[3] = (const float*)d_in[21];
    FcPar fp;
    fp.fcb[0] = (const float*)d_in[23];
    fp.fcb[1] = (const float*)d_in[26];
    const float* attd = (const float*)d_in[24];
    const float* attp = (const float*)d_in[27];
    float* out = (float*)d_out;

    cudaFuncSetAttribute(k_gcnmma, cudaFuncAttributeMaxDynamicSharedMemorySize, SMEM_G);
    cudaFuncSetAttribute(k_fcmma, cudaFuncAttributeMaxDynamicSharedMemorySize, SMEM_F);

    void* cntAddr = nullptr; cudaGetSymbolAddress(&cntAddr, g_cnt);
    void* spAddr = nullptr;  cudaGetSymbolAddress(&spAddr, g_sp);
    cudaMemsetAsync(cntAddr, 0, sizeof(int) * 4 * NN);
    cudaMemsetAsync(spAddr, 0, sizeof(float) * 4 * HH);

    dim3 eg((EE + 255) / 256, 4);
    k_hist4<<<eg, 256>>>(ip);
    k_scan<<<4, 1024>>>();
    k_scatter4<<<eg, 256>>>(ip, vp);
    k_convw6<<<dim3(64, 6), 256>>>(w6);

    k_spmm4<<<dim3((NN + 3) / 4, 4), 256>>>(h_d, h_p);
    k_gcnmma<<<dim3((NN + 127) / 128, 2, 4), 256, SMEM_G>>>(gp);
    k_fcmma<<<dim3((NN + 127) / 128, 2, 4), 256, SMEM_F>>>(fp);
    k_beta2<<<2, 256>>>(attd, attp);
    k_combine2<<<dim3(2048, 2), 256>>>(out);
}